// round 3
// baseline (speedup 1.0000x reference)
#include <cuda_runtime.h>

#define L 320
#define C 128
#define H 4
#define D 32
#define NPOS (L*L)
#define NPROJ 516   // 384 qkv + 4 pair + 128 gate

typedef unsigned long long ull;

// ---------------- scratch (device globals; no allocations allowed) ----------------
__device__ float g_zn[NPOS*C];        // layernormed z
__device__ float g_q[H*L*L*D];        // [(r*H+h)*L + i]*D + d   (q pre-scaled by 1/sqrt(D))
__device__ float g_k[H*L*L*D];
__device__ float g_v[H*L*L*D];
__device__ float g_pbT[H*L*L];        // [(h*L + j)*L + i] = pair_bias[i,j,h]
__device__ float g_gate[NPOS*C];      // sigmoid gate
__device__ float g_att[NPOS*C];       // gated attention output
__device__ float g_W[C*NPROJ];        // packed projection weights [c][n]

// ---------------- packed f32x2 helpers ----------------
__device__ __forceinline__ ull ffma2(ull a, ull b, ull c){
    ull d; asm("fma.rn.f32x2 %0, %1, %2, %3;" : "=l"(d) : "l"(a), "l"(b), "l"(c)); return d;
}
__device__ __forceinline__ ull fadd2(ull a, ull b){
    ull d; asm("add.rn.f32x2 %0, %1, %2;" : "=l"(d) : "l"(a), "l"(b)); return d;
}
__device__ __forceinline__ ull pack2(float x, float y){
    ull r; asm("mov.b64 %0, {%1, %2};" : "=l"(r) : "f"(x), "f"(y)); return r;
}
__device__ __forceinline__ float2 unpack2(ull v){
    float2 f; asm("mov.b64 {%0, %1}, %2;" : "=f"(f.x), "=f"(f.y) : "l"(v)); return f;
}

// ---------------- kernel 1: layernorm ----------------
__global__ void ln_kernel(const float* __restrict__ z,
                          const float* __restrict__ lng,
                          const float* __restrict__ lnb){
    int p = blockIdx.x;
    int t = threadIdx.x;        // 128 threads, one channel each
    float x = z[p*C + t];
    float s = x, s2 = x*x;
    #pragma unroll
    for (int o = 16; o; o >>= 1){
        s  += __shfl_xor_sync(0xFFFFFFFFu, s,  o);
        s2 += __shfl_xor_sync(0xFFFFFFFFu, s2, o);
    }
    __shared__ float ws[4], ws2[4];
    int w = t >> 5;
    if ((t & 31) == 0){ ws[w] = s; ws2[w] = s2; }
    __syncthreads();
    s  = ws[0] + ws[1] + ws[2] + ws[3];
    s2 = ws2[0] + ws2[1] + ws2[2] + ws2[3];
    float m = s * (1.f/C);
    float v = s2 * (1.f/C) - m*m;
    float r = rsqrtf(v + 1e-5f);
    g_zn[p*C + t] = (x - m) * r * lng[t] + lnb[t];
}

// ---------------- kernel 2: pack projection weights [c][n] ----------------
__global__ void pack_kernel(const float* __restrict__ Wqkv,
                            const float* __restrict__ Wpair,
                            const float* __restrict__ Wgate){
    int idx = blockIdx.x * blockDim.x + threadIdx.x;
    if (idx >= C*NPROJ) return;
    int c = idx / NPROJ, n = idx % NPROJ;
    float v;
    if (n < 384)      v = Wqkv[c*384 + n];
    else if (n < 388) v = Wpair[c*4 + (n-384)];
    else              v = Wgate[c*128 + (n-388)];
    g_W[idx] = v;
}

// ---------------- epilogue router for projection GEMM ----------------
__device__ __forceinline__ void epi_proj(int p, int n, float val,
                                         const float* __restrict__ bgate){
    if (n < 384){
        int part = n >> 7;          // 0=q 1=k 2=v
        int rem  = n & 127;
        int h = rem >> 5, d = rem & 31;
        int r = p / L, i = p - r*L;
        int idx = ((r*H + h)*L + i)*D + d;
        if (part == 0)      g_q[idx] = val * 0.17677669529663687f;  // 1/sqrt(32)
        else if (part == 1) g_k[idx] = val;
        else                g_v[idx] = val;
    } else if (n < 388){
        int h = n - 384;
        int i = p / L, j = p - i*L;
        g_pbT[(h*L + j)*L + i] = val;
    } else if (n < NPROJ){
        int c = n - 388;
        g_gate[p*C + c] = 1.f / (1.f + __expf(-(val + bgate[c])));
    }
}

// ---------------- GEMM: BM=128, BN=64, K=128 (chunks of 32), f32x2 micro-kernel ----------------
template<int MODE>
__global__ void __launch_bounds__(256)
gemm_kernel(const float* __restrict__ Wext,
            const float* __restrict__ bias,
            float* __restrict__ out){
    constexpr int NW = (MODE == 0) ? NPROJ : 128;
    const float* __restrict__ A = (MODE == 0) ? g_zn : g_att;
    const float* __restrict__ W = (MODE == 0) ? g_W  : Wext;

    const int n0 = blockIdx.x * 64;
    const int m0 = blockIdx.y * 128;
    __shared__ float As[32][132];   // [k][m], transposed, padded
    __shared__ float Ws[32][68];    // [k][n], padded

    int tid = threadIdx.x;
    int tx = tid & 15;              // n-group: 4 outputs
    int ty = tid >> 4;              // m-group: 8 outputs (4 pairs)

    ull acc[4][4];
    #pragma unroll
    for (int a = 0; a < 4; a++)
        #pragma unroll
        for (int b = 0; b < 4; b++) acc[a][b] = 0ull;

    for (int kc = 0; kc < 128; kc += 32){
        #pragma unroll
        for (int t = tid; t < 1024; t += 256){
            int m = t >> 3, c4 = (t & 7) * 4;
            float4 a = *(const float4*)&A[(m0 + m)*C + kc + c4];
            As[c4+0][m] = a.x; As[c4+1][m] = a.y;
            As[c4+2][m] = a.z; As[c4+3][m] = a.w;
        }
        if (MODE == 0 && n0 + 64 > NW){
            #pragma unroll
            for (int t = tid; t < 512; t += 256){
                int c = t >> 4, n4 = (t & 15) * 4;
                #pragma unroll
                for (int u = 0; u < 4; u++){
                    int n = n0 + n4 + u;
                    Ws[c][n4+u] = (n < NW) ? W[(kc + c)*NW + n] : 0.f;
                }
            }
        } else {
            #pragma unroll
            for (int t = tid; t < 512; t += 256){
                int c = t >> 4, n4 = (t & 15) * 4;
                *(float4*)&Ws[c][n4] = *(const float4*)&W[(kc + c)*NW + n0 + n4];
            }
        }
        __syncthreads();

        #pragma unroll 8
        for (int k = 0; k < 32; k++){
            ulonglong2 a01 = *(const ulonglong2*)&As[k][ty*8];
            ulonglong2 a23 = *(const ulonglong2*)&As[k][ty*8 + 4];
            float4 b = *(const float4*)&Ws[k][tx*4];
            ull bs0 = pack2(b.x, b.x), bs1 = pack2(b.y, b.y);
            ull bs2 = pack2(b.z, b.z), bs3 = pack2(b.w, b.w);
            acc[0][0] = ffma2(a01.x, bs0, acc[0][0]);
            acc[0][1] = ffma2(a01.x, bs1, acc[0][1]);
            acc[0][2] = ffma2(a01.x, bs2, acc[0][2]);
            acc[0][3] = ffma2(a01.x, bs3, acc[0][3]);
            acc[1][0] = ffma2(a01.y, bs0, acc[1][0]);
            acc[1][1] = ffma2(a01.y, bs1, acc[1][1]);
            acc[1][2] = ffma2(a01.y, bs2, acc[1][2]);
            acc[1][3] = ffma2(a01.y, bs3, acc[1][3]);
            acc[2][0] = ffma2(a23.x, bs0, acc[2][0]);
            acc[2][1] = ffma2(a23.x, bs1, acc[2][1]);
            acc[2][2] = ffma2(a23.x, bs2, acc[2][2]);
            acc[2][3] = ffma2(a23.x, bs3, acc[2][3]);
            acc[3][0] = ffma2(a23.y, bs0, acc[3][0]);
            acc[3][1] = ffma2(a23.y, bs1, acc[3][1]);
            acc[3][2] = ffma2(a23.y, bs2, acc[3][2]);
            acc[3][3] = ffma2(a23.y, bs3, acc[3][3]);
        }
        __syncthreads();
    }

    #pragma unroll
    for (int mp = 0; mp < 4; mp++){
        int m = m0 + ty*8 + mp*2;
        #pragma unroll
        for (int j = 0; j < 4; j++){
            int n = n0 + tx*4 + j;
            float2 v2 = unpack2(acc[mp][j]);
            if (MODE == 0){
                epi_proj(m,   n, v2.x, bias);
                epi_proj(m+1, n, v2.y, bias);
            } else {
                float bb = bias[n];
                out[(m  )*C + n] = v2.x + bb;
                out[(m+1)*C + n] = v2.y + bb;
            }
        }
    }
}

// ---------------- kernel 4: attention per (r,h) ----------------
// 640 threads: pair (i = tid>>1, jh = tid&1); each thread handles 160 j's.
__global__ void __launch_bounds__(640, 1)
attn_kernel(){
    extern __shared__ float sm[];
    float* Ks = sm;             // [320][32]
    float* Vs = sm + L*D;       // [320][32]

    int r = blockIdx.x, h = blockIdx.y;
    int tid = threadIdx.x;
    int i  = tid >> 1;
    int jh = tid & 1;
    int base = ((r*H + h)*L)*D;

    // cooperative K/V load (coalesced, contiguous 40KB each)
    {
        const float4* kg = (const float4*)&g_k[base];
        const float4* vg = (const float4*)&g_v[base];
        float4* Ks4 = (float4*)Ks;
        float4* Vs4 = (float4*)Vs;
        for (int t = tid; t < L*D/4; t += 640){ Ks4[t] = kg[t]; Vs4[t] = vg[t]; }
    }
    // Q row i as 16 f32x2 pairs
    ull q2[16];
    {
        const ulonglong2* qg = (const ulonglong2*)&g_q[base + i*D];
        #pragma unroll
        for (int t = 0; t < 8; t++){ ulonglong2 qq = qg[t]; q2[2*t] = qq.x; q2[2*t+1] = qq.y; }
    }
    __syncthreads();

    ull acc[16];
    #pragma unroll
    for (int t = 0; t < 16; t++) acc[t] = 0ull;
    float lsum = 0.f;

    const float* pb = &g_pbT[(h*L)*L + i];   // + j*L per step; coalesced over i

    const int j0 = jh * (L/2);
    #pragma unroll 2
    for (int jj = 0; jj < L/2; jj++){
        int j = j0 + jj;
        float biasv = __ldg(&pb[j*L]);
        const ulonglong2* kj = (const ulonglong2*)&Ks[j*D];
        // 4 independent accumulation chains (critical path 4 ffma2 = 16 cyc)
        ull s0 = 0ull, s1 = 0ull, s2 = 0ull, s3 = 0ull;
        {
            ulonglong2 ka0 = kj[0], ka1 = kj[1], ka2 = kj[2], ka3 = kj[3];
            ulonglong2 kb0 = kj[4], kb1 = kj[5], kb2 = kj[6], kb3 = kj[7];
            s0 = ffma2(q2[0],  ka0.x, s0); s0 = ffma2(q2[1],  ka0.y, s0);
            s1 = ffma2(q2[2],  ka1.x, s1); s1 = ffma2(q2[3],  ka1.y, s1);
            s2 = ffma2(q2[4],  ka2.x, s2); s2 = ffma2(q2[5],  ka2.y, s2);
            s3 = ffma2(q2[6],  ka3.x, s3); s3 = ffma2(q2[7],  ka3.y, s3);
            s0 = ffma2(q2[8],  kb0.x, s0); s0 = ffma2(q2[9],  kb0.y, s0);
            s1 = ffma2(q2[10], kb1.x, s1); s1 = ffma2(q2[11], kb1.y, s1);
            s2 = ffma2(q2[12], kb2.x, s2); s2 = ffma2(q2[13], kb2.y, s2);
            s3 = ffma2(q2[14], kb3.x, s3); s3 = ffma2(q2[15], kb3.y, s3);
        }
        float2 sf = unpack2(fadd2(fadd2(s0, s1), fadd2(s2, s3)));
        float s = sf.x + sf.y + biasv;
        s = fminf(s, 60.f);                 // scores are O(1); safety clamp only
        float p = __expf(s);
        lsum += p;
        ull p2 = pack2(p, p);
        const ulonglong2* vj = (const ulonglong2*)&Vs[j*D];
        #pragma unroll
        for (int t = 0; t < 8; t++){
            ulonglong2 vv = vj[t];
            acc[2*t]   = ffma2(p2, vv.x, acc[2*t]);
            acc[2*t+1] = ffma2(p2, vv.y, acc[2*t+1]);
        }
    }

    // combine the two j-halves; reuse K/V smem (stride 33 -> conflict-free)
    __syncthreads();
    float* buf = sm;
    if (jh == 1){
        float* b = &buf[i*33];
        #pragma unroll
        for (int t = 0; t < 16; t++){
            float2 v2 = unpack2(acc[t]);
            b[2*t] = v2.x; b[2*t+1] = v2.y;   // linear: b[d] = partial for dim d
        }
        b[32] = lsum;
    }
    __syncthreads();
    if (jh == 0){
        const float* b = &buf[i*33];
        float inv = 1.f / (lsum + b[32]);
        int p = r*L + i;
        const float4* g4 = (const float4*)&g_gate[p*C + h*D];
        float4* o4 = (float4*)&g_att[p*C + h*D];
        #pragma unroll
        for (int t = 0; t < 8; t++){
            float2 x = unpack2(acc[2*t]);     // d = 4t, 4t+1
            float2 y = unpack2(acc[2*t+1]);   // d = 4t+2, 4t+3
            float4 g = g4[t];
            float4 o;
            o.x = (x.x + b[4*t+0]) * inv * g.x;
            o.y = (x.y + b[4*t+1]) * inv * g.y;
            o.z = (y.x + b[4*t+2]) * inv * g.z;
            o.w = (y.y + b[4*t+3]) * inv * g.w;
            o4[t] = o;
        }
    }
}

// ---------------- launch ----------------
extern "C" void kernel_launch(void* const* d_in, const int* in_sizes, int n_in,
                              void* d_out, int out_size){
    const float* z     = (const float*)d_in[0];
    const float* ln_g  = (const float*)d_in[1];
    const float* ln_b  = (const float*)d_in[2];
    const float* Wqkv  = (const float*)d_in[3];
    const float* Wpair = (const float*)d_in[4];
    const float* Wgate = (const float*)d_in[5];
    const float* bgate = (const float*)d_in[6];
    const float* Wout  = (const float*)d_in[7];
    const float* bout  = (const float*)d_in[8];
    float* out = (float*)d_out;

    static bool attr_set = false;
    if (!attr_set){
        cudaFuncSetAttribute(attn_kernel, cudaFuncAttributeMaxDynamicSharedMemorySize,
                             2*L*D*(int)sizeof(float));
        attr_set = true;
    }

    ln_kernel<<<NPOS, 128>>>(z, ln_g, ln_b);
    pack_kernel<<<(C*NPROJ + 255)/256, 256>>>(Wqkv, Wpair, Wgate);
    gemm_kernel<0><<<dim3((NPROJ + 63)/64, NPOS/128), 256>>>(nullptr, bgate, nullptr);
    attn_kernel<<<dim3(L, H), 640, 2*L*D*sizeof(float)>>>();
    gemm_kernel<1><<<dim3(128/64, NPOS/128), 256>>>(Wout, bout, out);
}

// round 5
// speedup vs baseline: 1.1285x; 1.1285x over previous
#include <cuda_runtime.h>

#define L 320
#define C 128
#define H 4
#define D 32
#define NPOS (L*L)
#define NPROJ 516   // 384 qkv + 4 pair + 128 gate

typedef unsigned long long ull;

// ---------------- scratch (device globals; no allocations allowed) ----------------
__device__ float g_zn[NPOS*C];        // layernormed z
__device__ float g_q[H*L*L*D];        // [(r*H+h)*L + i]*D + d   (q pre-scaled by 1/sqrt(D))
__device__ float g_k[H*L*L*D];
__device__ float g_v[H*L*L*D];
__device__ float g_pbT[H*L*L];        // [(h*L + j)*L + i] = pair_bias[i,j,h]
__device__ float g_gate[NPOS*C];      // sigmoid gate
__device__ float g_att[NPOS*C];       // gated attention output
__device__ float g_W[C*NPROJ];        // packed projection weights [c][n]

// ---------------- packed f32x2 helpers ----------------
__device__ __forceinline__ ull ffma2(ull a, ull b, ull c){
    ull d; asm("fma.rn.f32x2 %0, %1, %2, %3;" : "=l"(d) : "l"(a), "l"(b), "l"(c)); return d;
}
__device__ __forceinline__ ull fadd2(ull a, ull b){
    ull d; asm("add.rn.f32x2 %0, %1, %2;" : "=l"(d) : "l"(a), "l"(b)); return d;
}
__device__ __forceinline__ ull pack2(float x, float y){
    ull r; asm("mov.b64 %0, {%1, %2};" : "=l"(r) : "f"(x), "f"(y)); return r;
}
__device__ __forceinline__ float2 unpack2(ull v){
    float2 f; asm("mov.b64 {%0, %1}, %2;" : "=f"(f.x), "=f"(f.y) : "l"(v)); return f;
}

// ---------------- kernel 1: layernorm ----------------
__global__ void ln_kernel(const float* __restrict__ z,
                          const float* __restrict__ lng,
                          const float* __restrict__ lnb){
    int p = blockIdx.x;
    int t = threadIdx.x;        // 128 threads, one channel each
    float x = z[p*C + t];
    float s = x, s2 = x*x;
    #pragma unroll
    for (int o = 16; o; o >>= 1){
        s  += __shfl_xor_sync(0xFFFFFFFFu, s,  o);
        s2 += __shfl_xor_sync(0xFFFFFFFFu, s2, o);
    }
    __shared__ float ws[4], ws2[4];
    int w = t >> 5;
    if ((t & 31) == 0){ ws[w] = s; ws2[w] = s2; }
    __syncthreads();
    s  = ws[0] + ws[1] + ws[2] + ws[3];
    s2 = ws2[0] + ws2[1] + ws2[2] + ws2[3];
    float m = s * (1.f/C);
    float v = s2 * (1.f/C) - m*m;
    float r = rsqrtf(v + 1e-5f);
    g_zn[p*C + t] = (x - m) * r * lng[t] + lnb[t];
}

// ---------------- kernel 2: pack projection weights [c][n] ----------------
__global__ void pack_kernel(const float* __restrict__ Wqkv,
                            const float* __restrict__ Wpair,
                            const float* __restrict__ Wgate){
    int idx = blockIdx.x * blockDim.x + threadIdx.x;
    if (idx >= C*NPROJ) return;
    int c = idx / NPROJ, n = idx % NPROJ;
    float v;
    if (n < 384)      v = Wqkv[c*384 + n];
    else if (n < 388) v = Wpair[c*4 + (n-384)];
    else              v = Wgate[c*128 + (n-388)];
    g_W[idx] = v;
}

// ---------------- epilogue router for projection GEMM ----------------
__device__ __forceinline__ void epi_proj(int p, int n, float val,
                                         const float* __restrict__ bgate){
    if (n < 384){
        int part = n >> 7;          // 0=q 1=k 2=v
        int rem  = n & 127;
        int h = rem >> 5, d = rem & 31;
        int r = p / L, i = p - r*L;
        int idx = ((r*H + h)*L + i)*D + d;
        if (part == 0)      g_q[idx] = val * 0.17677669529663687f;  // 1/sqrt(32)
        else if (part == 1) g_k[idx] = val;
        else                g_v[idx] = val;
    } else if (n < 388){
        int h = n - 384;
        int i = p / L, j = p - i*L;
        g_pbT[(h*L + j)*L + i] = val;
    } else if (n < NPROJ){
        int c = n - 388;
        g_gate[p*C + c] = 1.f / (1.f + __expf(-(val + bgate[c])));
    }
}

// ---------------- GEMM: BM=128, BN=64, K=128 (chunks of 32), f32x2 micro-kernel ----------------
template<int MODE>
__global__ void __launch_bounds__(256)
gemm_kernel(const float* __restrict__ Wext,
            const float* __restrict__ bias,
            float* __restrict__ out){
    constexpr int NW = (MODE == 0) ? NPROJ : 128;
    const float* __restrict__ A = (MODE == 0) ? g_zn : g_att;
    const float* __restrict__ W = (MODE == 0) ? g_W  : Wext;

    const int n0 = blockIdx.x * 64;
    const int m0 = blockIdx.y * 128;
    __shared__ float As[32][132];   // [k][m], transposed, padded
    __shared__ float Ws[32][68];    // [k][n], padded

    int tid = threadIdx.x;
    int tx = tid & 15;              // n-group: 4 outputs
    int ty = tid >> 4;              // m-group: 8 outputs (4 pairs)

    ull acc[4][4];
    #pragma unroll
    for (int a = 0; a < 4; a++)
        #pragma unroll
        for (int b = 0; b < 4; b++) acc[a][b] = 0ull;

    for (int kc = 0; kc < 128; kc += 32){
        #pragma unroll
        for (int t = tid; t < 1024; t += 256){
            int m = t >> 3, c4 = (t & 7) * 4;
            float4 a = *(const float4*)&A[(m0 + m)*C + kc + c4];
            As[c4+0][m] = a.x; As[c4+1][m] = a.y;
            As[c4+2][m] = a.z; As[c4+3][m] = a.w;
        }
        if (MODE == 0 && n0 + 64 > NW){
            #pragma unroll
            for (int t = tid; t < 512; t += 256){
                int c = t >> 4, n4 = (t & 15) * 4;
                #pragma unroll
                for (int u = 0; u < 4; u++){
                    int n = n0 + n4 + u;
                    Ws[c][n4+u] = (n < NW) ? W[(kc + c)*NW + n] : 0.f;
                }
            }
        } else {
            #pragma unroll
            for (int t = tid; t < 512; t += 256){
                int c = t >> 4, n4 = (t & 15) * 4;
                *(float4*)&Ws[c][n4] = *(const float4*)&W[(kc + c)*NW + n0 + n4];
            }
        }
        __syncthreads();

        #pragma unroll 8
        for (int k = 0; k < 32; k++){
            ulonglong2 a01 = *(const ulonglong2*)&As[k][ty*8];
            ulonglong2 a23 = *(const ulonglong2*)&As[k][ty*8 + 4];
            float4 b = *(const float4*)&Ws[k][tx*4];
            ull bs0 = pack2(b.x, b.x), bs1 = pack2(b.y, b.y);
            ull bs2 = pack2(b.z, b.z), bs3 = pack2(b.w, b.w);
            acc[0][0] = ffma2(a01.x, bs0, acc[0][0]);
            acc[0][1] = ffma2(a01.x, bs1, acc[0][1]);
            acc[0][2] = ffma2(a01.x, bs2, acc[0][2]);
            acc[0][3] = ffma2(a01.x, bs3, acc[0][3]);
            acc[1][0] = ffma2(a01.y, bs0, acc[1][0]);
            acc[1][1] = ffma2(a01.y, bs1, acc[1][1]);
            acc[1][2] = ffma2(a01.y, bs2, acc[1][2]);
            acc[1][3] = ffma2(a01.y, bs3, acc[1][3]);
            acc[2][0] = ffma2(a23.x, bs0, acc[2][0]);
            acc[2][1] = ffma2(a23.x, bs1, acc[2][1]);
            acc[2][2] = ffma2(a23.x, bs2, acc[2][2]);
            acc[2][3] = ffma2(a23.x, bs3, acc[2][3]);
            acc[3][0] = ffma2(a23.y, bs0, acc[3][0]);
            acc[3][1] = ffma2(a23.y, bs1, acc[3][1]);
            acc[3][2] = ffma2(a23.y, bs2, acc[3][2]);
            acc[3][3] = ffma2(a23.y, bs3, acc[3][3]);
        }
        __syncthreads();
    }

    #pragma unroll
    for (int mp = 0; mp < 4; mp++){
        int m = m0 + ty*8 + mp*2;
        #pragma unroll
        for (int j = 0; j < 4; j++){
            int n = n0 + tx*4 + j;
            float2 v2 = unpack2(acc[mp][j]);
            if (MODE == 0){
                epi_proj(m,   n, v2.x, bias);
                epi_proj(m+1, n, v2.y, bias);
            } else {
                float bb = bias[n];
                out[(m  )*C + n] = v2.x + bb;
                out[(m+1)*C + n] = v2.y + bb;
            }
        }
    }
}

// ---------------- kernel 4: attention per (r,h) ----------------
// 160 threads; each thread owns TWO i-rows (tid, tid+160). All lanes in a warp
// share j -> broadcast LDS; K_j/V_j regs reused across both rows (fma:lds = 4:1).
__global__ void __launch_bounds__(160, 2)
attn_kernel(){
    extern __shared__ float sm[];
    float* Ks = sm;             // [320][32]
    float* Vs = sm + L*D;       // [320][32]

    int r = blockIdx.x, h = blockIdx.y;
    int tid = threadIdx.x;
    int i0 = tid, i1 = tid + 160;
    int base = ((r*H + h)*L)*D;

    // cooperative K/V load (coalesced, contiguous 40KB each)
    {
        const float4* kg = (const float4*)&g_k[base];
        const float4* vg = (const float4*)&g_v[base];
        float4* Ks4 = (float4*)Ks;
        float4* Vs4 = (float4*)Vs;
        #pragma unroll
        for (int t = tid; t < L*D/4; t += 160){ Ks4[t] = kg[t]; Vs4[t] = vg[t]; }
    }
    // Q rows i0, i1 as f32x2 pairs
    ull qa[16], qb[16];
    {
        const ulonglong2* qg0 = (const ulonglong2*)&g_q[base + i0*D];
        const ulonglong2* qg1 = (const ulonglong2*)&g_q[base + i1*D];
        #pragma unroll
        for (int t = 0; t < 8; t++){
            ulonglong2 qq0 = qg0[t]; qa[2*t] = qq0.x; qa[2*t+1] = qq0.y;
            ulonglong2 qq1 = qg1[t]; qb[2*t] = qq1.x; qb[2*t+1] = qq1.y;
        }
    }
    __syncthreads();

    ull acca[16], accb[16];
    #pragma unroll
    for (int t = 0; t < 16; t++){ acca[t] = 0ull; accb[t] = 0ull; }
    float lsa = 0.f, lsb = 0.f;

    const float* pb = &g_pbT[(h*L)*L];   // pb[j*L + i]

    #pragma unroll 1
    for (int j = 0; j < L; j++){
        float biasa = __ldg(&pb[j*L + i0]);
        float biasb = __ldg(&pb[j*L + i1]);
        const ulonglong2* kj = (const ulonglong2*)&Ks[j*D];
        // 4 chains per row, 8 independent chains total
        ull sa0 = 0ull, sa1 = 0ull, sa2 = 0ull, sa3 = 0ull;
        ull sb0 = 0ull, sb1 = 0ull, sb2 = 0ull, sb3 = 0ull;
        {
            ulonglong2 k0 = kj[0], k1 = kj[1], k2 = kj[2], k3 = kj[3];
            ulonglong2 k4 = kj[4], k5 = kj[5], k6 = kj[6], k7 = kj[7];
            sa0 = ffma2(qa[0],  k0.x, sa0); sb0 = ffma2(qb[0],  k0.x, sb0);
            sa0 = ffma2(qa[1],  k0.y, sa0); sb0 = ffma2(qb[1],  k0.y, sb0);
            sa1 = ffma2(qa[2],  k1.x, sa1); sb1 = ffma2(qb[2],  k1.x, sb1);
            sa1 = ffma2(qa[3],  k1.y, sa1); sb1 = ffma2(qb[3],  k1.y, sb1);
            sa2 = ffma2(qa[4],  k2.x, sa2); sb2 = ffma2(qb[4],  k2.x, sb2);
            sa2 = ffma2(qa[5],  k2.y, sa2); sb2 = ffma2(qb[5],  k2.y, sb2);
            sa3 = ffma2(qa[6],  k3.x, sa3); sb3 = ffma2(qb[6],  k3.x, sb3);
            sa3 = ffma2(qa[7],  k3.y, sa3); sb3 = ffma2(qb[7],  k3.y, sb3);
            sa0 = ffma2(qa[8],  k4.x, sa0); sb0 = ffma2(qb[8],  k4.x, sb0);
            sa0 = ffma2(qa[9],  k4.y, sa0); sb0 = ffma2(qb[9],  k4.y, sb0);
            sa1 = ffma2(qa[10], k5.x, sa1); sb1 = ffma2(qb[10], k5.x, sb1);
            sa1 = ffma2(qa[11], k5.y, sa1); sb1 = ffma2(qb[11], k5.y, sb1);
            sa2 = ffma2(qa[12], k6.x, sa2); sb2 = ffma2(qb[12], k6.x, sb2);
            sa2 = ffma2(qa[13], k6.y, sa2); sb2 = ffma2(qb[13], k6.y, sb2);
            sa3 = ffma2(qa[14], k7.x, sa3); sb3 = ffma2(qb[14], k7.x, sb3);
            sa3 = ffma2(qa[15], k7.y, sa3); sb3 = ffma2(qb[15], k7.y, sb3);
        }
        float2 fa = unpack2(fadd2(fadd2(sa0, sa1), fadd2(sa2, sa3)));
        float2 fb = unpack2(fadd2(fadd2(sb0, sb1), fadd2(sb2, sb3)));
        float scA = fminf(fa.x + fa.y + biasa, 60.f);
        float scB = fminf(fb.x + fb.y + biasb, 60.f);
        float pA = __expf(scA);
        float pB = __expf(scB);
        lsa += pA; lsb += pB;
        ull pa2 = pack2(pA, pA);
        ull pb2 = pack2(pB, pB);
        const ulonglong2* vj = (const ulonglong2*)&Vs[j*D];
        #pragma unroll
        for (int t = 0; t < 8; t++){
            ulonglong2 vv = vj[t];
            acca[2*t]   = ffma2(pa2, vv.x, acca[2*t]);
            accb[2*t]   = ffma2(pb2, vv.x, accb[2*t]);
            acca[2*t+1] = ffma2(pa2, vv.y, acca[2*t+1]);
            accb[2*t+1] = ffma2(pb2, vv.y, accb[2*t+1]);
        }
    }

    // epilogue: both rows
    {
        float inv = 1.f / lsa;
        int p = r*L + i0;
        const float4* g4 = (const float4*)&g_gate[p*C + h*D];
        float4* o4 = (float4*)&g_att[p*C + h*D];
        #pragma unroll
        for (int t = 0; t < 8; t++){
            float2 x = unpack2(acca[2*t]);
            float2 y = unpack2(acca[2*t+1]);
            float4 g = g4[t];
            float4 o;
            o.x = x.x * inv * g.x;
            o.y = x.y * inv * g.y;
            o.z = y.x * inv * g.z;
            o.w = y.y * inv * g.w;
            o4[t] = o;
        }
    }
    {
        float inv = 1.f / lsb;
        int p = r*L + i1;
        const float4* g4 = (const float4*)&g_gate[p*C + h*D];
        float4* o4 = (float4*)&g_att[p*C + h*D];
        #pragma unroll
        for (int t = 0; t < 8; t++){
            float2 x = unpack2(accb[2*t]);
            float2 y = unpack2(accb[2*t+1]);
            float4 g = g4[t];
            float4 o;
            o.x = x.x * inv * g.x;
            o.y = x.y * inv * g.y;
            o.z = y.x * inv * g.z;
            o.w = y.y * inv * g.w;
            o4[t] = o;
        }
    }
}

// ---------------- launch ----------------
extern "C" void kernel_launch(void* const* d_in, const int* in_sizes, int n_in,
                              void* d_out, int out_size){
    const float* z     = (const float*)d_in[0];
    const float* ln_g  = (const float*)d_in[1];
    const float* ln_b  = (const float*)d_in[2];
    const float* Wqkv  = (const float*)d_in[3];
    const float* Wpair = (const float*)d_in[4];
    const float* Wgate = (const float*)d_in[5];
    const float* bgate = (const float*)d_in[6];
    const float* Wout  = (const float*)d_in[7];
    const float* bout  = (const float*)d_in[8];
    float* out = (float*)d_out;

    static bool attr_set = false;
    if (!attr_set){
        cudaFuncSetAttribute(attn_kernel, cudaFuncAttributeMaxDynamicSharedMemorySize,
                             2*L*D*(int)sizeof(float));
        attr_set = true;
    }

    ln_kernel<<<NPOS, 128>>>(z, ln_g, ln_b);
    pack_kernel<<<(C*NPROJ + 255)/256, 256>>>(Wqkv, Wpair, Wgate);
    gemm_kernel<0><<<dim3((NPROJ + 63)/64, NPOS/128), 256>>>(nullptr, bgate, nullptr);
    attn_kernel<<<dim3(L, H), 160, 2*L*D*sizeof(float)>>>();
    gemm_kernel<1><<<dim3(128/64, NPOS/128), 256>>>(Wout, bout, out);
}

// round 7
// speedup vs baseline: 1.9578x; 1.7349x over previous
#include <cuda_runtime.h>
#include <cstdint>

#define L 320
#define C 128
#define H 4
#define D 32
#define NPOS (L*L)
#define NPROJ 516   // 384 qkv + 4 pair + 128 gate

typedef unsigned long long ull;

// ---------------- scratch (device globals; no allocations allowed) ----------------
__device__ float g_zn[NPOS*C];        // layernormed z
__device__ float g_q[H*L*L*D];        // [(r*H+h)*L + i]*D + d   (q pre-scaled by 1/sqrt(D))
__device__ float g_k[H*L*L*D];        // [(r*H+h)*L + j]*D + d
__device__ float g_v[H*L*L*D];        // [(r*H+h)*L + j]*D + d
__device__ float g_pbI[H*L*L];        // [(h*L + i)*L + j] = pair_bias[i,j,h]
__device__ float g_gate[NPOS*C];      // sigmoid gate
__device__ float g_att[NPOS*C];       // gated attention output
__device__ float g_W[C*NPROJ];        // packed projection weights [c][n]

// ---------------- packed f32x2 helpers (FFMA2 GEMMs) ----------------
__device__ __forceinline__ ull ffma2(ull a, ull b, ull c){
    ull d; asm("fma.rn.f32x2 %0, %1, %2, %3;" : "=l"(d) : "l"(a), "l"(b), "l"(c)); return d;
}
__device__ __forceinline__ ull pack2(float x, float y){
    ull r; asm("mov.b64 %0, {%1, %2};" : "=l"(r) : "f"(x), "f"(y)); return r;
}
__device__ __forceinline__ float2 unpack2(ull v){
    float2 f; asm("mov.b64 {%0, %1}, %2;" : "=f"(f.x), "=f"(f.y) : "l"(v)); return f;
}

// ---------------- tf32 mma.sync helpers ----------------
__device__ __forceinline__ float f2tf32(float x){
    uint32_t r; asm("cvt.rna.tf32.f32 %0, %1;" : "=r"(r) : "f"(x));
    return __uint_as_float(r);
}
__device__ __forceinline__ void mma8(float& d0, float& d1, float& d2, float& d3,
                                     uint32_t a0, uint32_t a1, uint32_t a2, uint32_t a3,
                                     uint32_t b0, uint32_t b1){
    asm("mma.sync.aligned.m16n8k8.row.col.f32.tf32.tf32.f32 "
        "{%0,%1,%2,%3}, {%4,%5,%6,%7}, {%8,%9}, {%0,%1,%2,%3};"
        : "+f"(d0), "+f"(d1), "+f"(d2), "+f"(d3)
        : "r"(a0), "r"(a1), "r"(a2), "r"(a3), "r"(b0), "r"(b1));
}

// ---------------- kernel 1: layernorm ----------------
__global__ void ln_kernel(const float* __restrict__ z,
                          const float* __restrict__ lng,
                          const float* __restrict__ lnb){
    int p = blockIdx.x;
    int t = threadIdx.x;
    float x = z[p*C + t];
    float s = x, s2 = x*x;
    #pragma unroll
    for (int o = 16; o; o >>= 1){
        s  += __shfl_xor_sync(0xFFFFFFFFu, s,  o);
        s2 += __shfl_xor_sync(0xFFFFFFFFu, s2, o);
    }
    __shared__ float ws[4], ws2[4];
    int w = t >> 5;
    if ((t & 31) == 0){ ws[w] = s; ws2[w] = s2; }
    __syncthreads();
    s  = ws[0] + ws[1] + ws[2] + ws[3];
    s2 = ws2[0] + ws2[1] + ws2[2] + ws2[3];
    float m = s * (1.f/C);
    float v = s2 * (1.f/C) - m*m;
    float r = rsqrtf(v + 1e-5f);
    g_zn[p*C + t] = (x - m) * r * lng[t] + lnb[t];
}

// ---------------- kernel 2: pack projection weights [c][n] ----------------
__global__ void pack_kernel(const float* __restrict__ Wqkv,
                            const float* __restrict__ Wpair,
                            const float* __restrict__ Wgate){
    int idx = blockIdx.x * blockDim.x + threadIdx.x;
    if (idx >= C*NPROJ) return;
    int c = idx / NPROJ, n = idx % NPROJ;
    float v;
    if (n < 384)      v = Wqkv[c*384 + n];
    else if (n < 388) v = Wpair[c*4 + (n-384)];
    else              v = Wgate[c*128 + (n-388)];
    g_W[idx] = v;
}

// ---------------- epilogue router for projection GEMM ----------------
__device__ __forceinline__ void epi_proj(int p, int n, float val,
                                         const float* __restrict__ bgate){
    if (n < 384){
        int part = n >> 7;          // 0=q 1=k 2=v
        int rem  = n & 127;
        int h = rem >> 5, d = rem & 31;
        int r = p / L, i = p - r*L;
        int idx = ((r*H + h)*L + i)*D + d;
        if (part == 0)      g_q[idx] = val * 0.17677669529663687f;  // 1/sqrt(32)
        else if (part == 1) g_k[idx] = val;
        else                g_v[idx] = val;
    } else if (n < 388){
        int h = n - 384;
        int i = p / L, j = p - i*L;
        g_pbI[(h*L + i)*L + j] = val;
    } else if (n < NPROJ){
        int c = n - 388;
        g_gate[p*C + c] = 1.f / (1.f + __expf(-(val + bgate[c])));
    }
}

// ---------------- GEMM: BM=128, BN=64, K=128, f32x2 micro-kernel ----------------
template<int MODE>
__global__ void __launch_bounds__(256)
gemm_kernel(const float* __restrict__ Wext,
            const float* __restrict__ bias,
            float* __restrict__ out){
    constexpr int NW = (MODE == 0) ? NPROJ : 128;
    const float* __restrict__ A = (MODE == 0) ? g_zn : g_att;
    const float* __restrict__ W = (MODE == 0) ? g_W  : Wext;

    const int n0 = blockIdx.x * 64;
    const int m0 = blockIdx.y * 128;
    __shared__ float As[32][132];
    __shared__ float Ws[32][68];

    int tid = threadIdx.x;
    int tx = tid & 15;
    int ty = tid >> 4;

    ull acc[4][4];
    #pragma unroll
    for (int a = 0; a < 4; a++)
        #pragma unroll
        for (int b = 0; b < 4; b++) acc[a][b] = 0ull;

    for (int kc = 0; kc < 128; kc += 32){
        #pragma unroll
        for (int t = tid; t < 1024; t += 256){
            int m = t >> 3, c4 = (t & 7) * 4;
            float4 a = *(const float4*)&A[(m0 + m)*C + kc + c4];
            As[c4+0][m] = a.x; As[c4+1][m] = a.y;
            As[c4+2][m] = a.z; As[c4+3][m] = a.w;
        }
        if (MODE == 0 && n0 + 64 > NW){
            #pragma unroll
            for (int t = tid; t < 512; t += 256){
                int c = t >> 4, n4 = (t & 15) * 4;
                #pragma unroll
                for (int u = 0; u < 4; u++){
                    int n = n0 + n4 + u;
                    Ws[c][n4+u] = (n < NW) ? W[(kc + c)*NW + n] : 0.f;
                }
            }
        } else {
            #pragma unroll
            for (int t = tid; t < 512; t += 256){
                int c = t >> 4, n4 = (t & 15) * 4;
                *(float4*)&Ws[c][n4] = *(const float4*)&W[(kc + c)*NW + n0 + n4];
            }
        }
        __syncthreads();

        #pragma unroll 8
        for (int k = 0; k < 32; k++){
            ulonglong2 a01 = *(const ulonglong2*)&As[k][ty*8];
            ulonglong2 a23 = *(const ulonglong2*)&As[k][ty*8 + 4];
            float4 b = *(const float4*)&Ws[k][tx*4];
            ull bs0 = pack2(b.x, b.x), bs1 = pack2(b.y, b.y);
            ull bs2 = pack2(b.z, b.z), bs3 = pack2(b.w, b.w);
            acc[0][0] = ffma2(a01.x, bs0, acc[0][0]);
            acc[0][1] = ffma2(a01.x, bs1, acc[0][1]);
            acc[0][2] = ffma2(a01.x, bs2, acc[0][2]);
            acc[0][3] = ffma2(a01.x, bs3, acc[0][3]);
            acc[1][0] = ffma2(a01.y, bs0, acc[1][0]);
            acc[1][1] = ffma2(a01.y, bs1, acc[1][1]);
            acc[1][2] = ffma2(a01.y, bs2, acc[1][2]);
            acc[1][3] = ffma2(a01.y, bs3, acc[1][3]);
            acc[2][0] = ffma2(a23.x, bs0, acc[2][0]);
            acc[2][1] = ffma2(a23.x, bs1, acc[2][1]);
            acc[2][2] = ffma2(a23.x, bs2, acc[2][2]);
            acc[2][3] = ffma2(a23.x, bs3, acc[2][3]);
            acc[3][0] = ffma2(a23.y, bs0, acc[3][0]);
            acc[3][1] = ffma2(a23.y, bs1, acc[3][1]);
            acc[3][2] = ffma2(a23.y, bs2, acc[3][2]);
            acc[3][3] = ffma2(a23.y, bs3, acc[3][3]);
        }
        __syncthreads();
    }

    #pragma unroll
    for (int mp = 0; mp < 4; mp++){
        int m = m0 + ty*8 + mp*2;
        #pragma unroll
        for (int j = 0; j < 4; j++){
            int n = n0 + tx*4 + j;
            float2 v2 = unpack2(acc[mp][j]);
            if (MODE == 0){
                epi_proj(m,   n, v2.x, bias);
                epi_proj(m+1, n, v2.y, bias);
            } else {
                float bb = bias[n];
                out[(m  )*C + n] = v2.x + bb;
                out[(m+1)*C + n] = v2.y + bb;
            }
        }
    }
}

// ---------------- kernel 4: tf32 mma.sync flash attention ----------------
// CTA = (r,h): 640 threads = 20 warps; warp w owns i-rows [16w, 16w+16).
// K,V in smem (stride 36 floats: conflict-free S-phase B frags), tf32-converted.
// Per 64-j chunk: S = Q.K^T (8 ntiles x 4 ksteps mma), bias+exp (tf32-rounded
// BEFORE lsum so normalization matches MMA operand), P->A frags via shfl,
// O += P.V (8 ksteps x 4 ntiles mma).
#define KV_STRIDE 36
#define SMEM_ATTN (2*L*KV_STRIDE*4)

__global__ void __launch_bounds__(640, 1)
attn_kernel(){
    extern __shared__ float sm[];
    float* Ks = sm;                 // [320][36]
    float* Vs = sm + L*KV_STRIDE;   // [320][36]

    const int tid = threadIdx.x;
    const int lane = tid & 31;
    const int g = lane >> 2;        // 0..7
    const int qr = lane & 3;        // 0..3
    const int i0 = (tid >> 5) * 16; // warp's row base
    const int r = blockIdx.x, h = blockIdx.y;
    const int rh = r*H + h;

    // ---- fill K/V smem (tf32-converted), coalesced float4 ----
    {
        const float4* kg = (const float4*)&g_k[(size_t)rh*L*D];
        const float4* vg = (const float4*)&g_v[(size_t)rh*L*D];
        for (int u = tid; u < L*D/4; u += 640){
            int j = u >> 3, d4 = (u & 7) << 2;
            float4 kv = kg[u];
            float4 vv = vg[u];
            float* kd = &Ks[j*KV_STRIDE + d4];
            float* vd = &Vs[j*KV_STRIDE + d4];
            kd[0] = f2tf32(kv.x); kd[1] = f2tf32(kv.y);
            kd[2] = f2tf32(kv.z); kd[3] = f2tf32(kv.w);
            vd[0] = f2tf32(vv.x); vd[1] = f2tf32(vv.y);
            vd[2] = f2tf32(vv.z); vd[3] = f2tf32(vv.w);
        }
    }

    // ---- Q fragments (register-resident, tf32) ----
    uint32_t qa[4][4];
    {
        const float* qbase = g_q + ((size_t)rh*L + i0)*D;
        #pragma unroll
        for (int t = 0; t < 4; t++){
            qa[t][0] = __float_as_uint(f2tf32(__ldg(&qbase[(g   )*D + 8*t + qr    ])));
            qa[t][1] = __float_as_uint(f2tf32(__ldg(&qbase[(g+8 )*D + 8*t + qr    ])));
            qa[t][2] = __float_as_uint(f2tf32(__ldg(&qbase[(g   )*D + 8*t + qr + 4])));
            qa[t][3] = __float_as_uint(f2tf32(__ldg(&qbase[(g+8 )*D + 8*t + qr + 4])));
        }
    }
    __syncthreads();

    const float* bp0 = g_pbI + ((size_t)(h*L + i0 + g    ))*L;  // row g bias
    const float* bp1 = g_pbI + ((size_t)(h*L + i0 + g + 8))*L;  // row g+8 bias

    float o[4][4];
    #pragma unroll
    for (int n = 0; n < 4; n++)
        #pragma unroll
        for (int q = 0; q < 4; q++) o[n][q] = 0.f;
    float lsum0 = 0.f, lsum1 = 0.f;

    const int srcA = (lane & ~3) | (qr >> 1);
    const int srcB = srcA + 2;
    const bool oddl = lane & 1;

    for (int c = 0; c < 5; c++){
        const int jc = 64*c;
        // ---- S phase: 8 ntiles ----
        float pr0[8], pr1[8], pr2[8], pr3[8];
        #pragma unroll
        for (int n = 0; n < 8; n++){
            float s0 = 0.f, s1 = 0.f, s2 = 0.f, s3 = 0.f;
            const float* kb = &Ks[(jc + 8*n + g)*KV_STRIDE + qr];
            #pragma unroll
            for (int t = 0; t < 4; t++){
                uint32_t b0 = __float_as_uint(kb[8*t]);
                uint32_t b1 = __float_as_uint(kb[8*t + 4]);
                mma8(s0, s1, s2, s3, qa[t][0], qa[t][1], qa[t][2], qa[t][3], b0, b1);
            }
            int j0 = jc + 8*n + qr*2;
            float2 ba = *(const float2*)&bp0[j0];
            float2 bb = *(const float2*)&bp1[j0];
            float p0 = f2tf32(__expf(fminf(s0 + ba.x, 60.f)));
            float p1 = f2tf32(__expf(fminf(s1 + ba.y, 60.f)));
            float p2 = f2tf32(__expf(fminf(s2 + bb.x, 60.f)));
            float p3 = f2tf32(__expf(fminf(s3 + bb.y, 60.f)));
            lsum0 += p0 + p1;
            lsum1 += p2 + p3;
            pr0[n] = p0; pr1[n] = p1; pr2[n] = p2; pr3[n] = p3;
        }
        // ---- PV phase: 8 ksteps x 4 ntiles ----
        #pragma unroll
        for (int t = 0; t < 8; t++){
            // P fragment -> A fragment via quad shuffles
            float v0a = __shfl_sync(0xFFFFFFFFu, pr0[t], srcA);
            float v1a = __shfl_sync(0xFFFFFFFFu, pr1[t], srcA);
            float v2a = __shfl_sync(0xFFFFFFFFu, pr2[t], srcA);
            float v3a = __shfl_sync(0xFFFFFFFFu, pr3[t], srcA);
            float v0b = __shfl_sync(0xFFFFFFFFu, pr0[t], srcB);
            float v1b = __shfl_sync(0xFFFFFFFFu, pr1[t], srcB);
            float v2b = __shfl_sync(0xFFFFFFFFu, pr2[t], srcB);
            float v3b = __shfl_sync(0xFFFFFFFFu, pr3[t], srcB);
            uint32_t A0 = __float_as_uint(oddl ? v1a : v0a);
            uint32_t A1 = __float_as_uint(oddl ? v3a : v2a);
            uint32_t A2 = __float_as_uint(oddl ? v1b : v0b);
            uint32_t A3 = __float_as_uint(oddl ? v3b : v2b);
            const float* vb0 = &Vs[(jc + 8*t + qr    )*KV_STRIDE + g];
            const float* vb1 = &Vs[(jc + 8*t + qr + 4)*KV_STRIDE + g];
            #pragma unroll
            for (int n = 0; n < 4; n++){
                uint32_t b0 = __float_as_uint(vb0[8*n]);
                uint32_t b1 = __float_as_uint(vb1[8*n]);
                mma8(o[n][0], o[n][1], o[n][2], o[n][3], A0, A1, A2, A3, b0, b1);
            }
        }
    }

    // ---- row sums across the quad ----
    lsum0 += __shfl_xor_sync(0xFFFFFFFFu, lsum0, 1);
    lsum0 += __shfl_xor_sync(0xFFFFFFFFu, lsum0, 2);
    lsum1 += __shfl_xor_sync(0xFFFFFFFFu, lsum1, 1);
    lsum1 += __shfl_xor_sync(0xFFFFFFFFu, lsum1, 2);
    float inv0 = 1.f / lsum0;
    float inv1 = 1.f / lsum1;

    // ---- gated output ----
    int ig0 = i0 + g, ig1 = i0 + g + 8;
    size_t ob0 = (size_t)(r*L + ig0)*C + h*D;
    size_t ob1 = (size_t)(r*L + ig1)*C + h*D;
    #pragma unroll
    for (int n = 0; n < 4; n++){
        int d0 = 8*n + qr*2;
        float2 g0 = *(const float2*)&g_gate[ob0 + d0];
        float2 g1 = *(const float2*)&g_gate[ob1 + d0];
        float2 w0, w1;
        w0.x = o[n][0] * inv0 * g0.x;
        w0.y = o[n][1] * inv0 * g0.y;
        w1.x = o[n][2] * inv1 * g1.x;
        w1.y = o[n][3] * inv1 * g1.y;
        *(float2*)&g_att[ob0 + d0] = w0;
        *(float2*)&g_att[ob1 + d0] = w1;
    }
}

// ---------------- launch ----------------
extern "C" void kernel_launch(void* const* d_in, const int* in_sizes, int n_in,
                              void* d_out, int out_size){
    const float* z     = (const float*)d_in[0];
    const float* ln_g  = (const float*)d_in[1];
    const float* ln_b  = (const float*)d_in[2];
    const float* Wqkv  = (const float*)d_in[3];
    const float* Wpair = (const float*)d_in[4];
    const float* Wgate = (const float*)d_in[5];
    const float* bgate = (const float*)d_in[6];
    const float* Wout  = (const float*)d_in[7];
    const float* bout  = (const float*)d_in[8];
    float* out = (float*)d_out;

    static bool attr_set = false;
    if (!attr_set){
        cudaFuncSetAttribute(attn_kernel, cudaFuncAttributeMaxDynamicSharedMemorySize,
                             SMEM_ATTN);
        attr_set = true;
    }

    ln_kernel<<<NPOS, 128>>>(z, ln_g, ln_b);
    pack_kernel<<<(C*NPROJ + 255)/256, 256>>>(Wqkv, Wpair, Wgate);
    gemm_kernel<0><<<dim3((NPROJ + 63)/64, NPOS/128), 256>>>(nullptr, bgate, nullptr);
    attn_kernel<<<dim3(L, H), 640, SMEM_ATTN>>>();
    gemm_kernel<1><<<dim3(128/64, NPOS/128), 256>>>(Wout, bout, out);
}

// round 10
// speedup vs baseline: 2.2695x; 1.1592x over previous
#include <cuda_runtime.h>
#include <cstdint>

#define L 320
#define C 128
#define H 4
#define D 32
#define NPOS (L*L)
#define NW2 512   // 384 qkv + 128 gate (pair handled separately)

typedef unsigned long long ull;

// ---------------- scratch (device globals; no allocations allowed) ----------------
__device__ float g_zn[NPOS*C];        // layernormed z (tf32-rounded)
__device__ float g_q[H*L*L*D];        // [(r*H+h)*L + i]*D + d   (q pre-scaled by 1/sqrt(D))
__device__ float g_k[H*L*L*D];
__device__ float g_v[H*L*L*D];
__device__ float g_pbI[H*L*L];        // [(h*L + i)*L + j] = pair_bias[i,j,h]
__device__ float g_gate[NPOS*C];      // sigmoid gate
__device__ float g_att[NPOS*C];       // gated attention output
__device__ float g_W[C*NW2];          // packed [c][n] = qkv|gate weights (tf32-rounded)

// ---------------- packed f32x2 helpers (FFMA2 output GEMM) ----------------
__device__ __forceinline__ ull ffma2(ull a, ull b, ull c){
    ull d; asm("fma.rn.f32x2 %0, %1, %2, %3;" : "=l"(d) : "l"(a), "l"(b), "l"(c)); return d;
}
__device__ __forceinline__ ull pack2(float x, float y){
    ull r; asm("mov.b64 %0, {%1, %2};" : "=l"(r) : "f"(x), "f"(y)); return r;
}
__device__ __forceinline__ float2 unpack2(ull v){
    float2 f; asm("mov.b64 {%0, %1}, %2;" : "=f"(f.x), "=f"(f.y) : "l"(v)); return f;
}

// ---------------- tf32 mma.sync helpers ----------------
__device__ __forceinline__ float f2tf32(float x){
    uint32_t r; asm("cvt.rna.tf32.f32 %0, %1;" : "=r"(r) : "f"(x));
    return __uint_as_float(r);
}
__device__ __forceinline__ void mma8(float& d0, float& d1, float& d2, float& d3,
                                     uint32_t a0, uint32_t a1, uint32_t a2, uint32_t a3,
                                     uint32_t b0, uint32_t b1){
    asm("mma.sync.aligned.m16n8k8.row.col.f32.tf32.tf32.f32 "
        "{%0,%1,%2,%3}, {%4,%5,%6,%7}, {%8,%9}, {%0,%1,%2,%3};"
        : "+f"(d0), "+f"(d1), "+f"(d2), "+f"(d3)
        : "r"(a0), "r"(a1), "r"(a2), "r"(a3), "r"(b0), "r"(b1));
}

// ---------------- kernel 1: layernorm (stores tf32-rounded zn) ----------------
__global__ void ln_kernel(const float* __restrict__ z,
                          const float* __restrict__ lng,
                          const float* __restrict__ lnb){
    int p = blockIdx.x;
    int t = threadIdx.x;
    float x = z[p*C + t];
    float s = x, s2 = x*x;
    #pragma unroll
    for (int o = 16; o; o >>= 1){
        s  += __shfl_xor_sync(0xFFFFFFFFu, s,  o);
        s2 += __shfl_xor_sync(0xFFFFFFFFu, s2, o);
    }
    __shared__ float ws[4], ws2[4];
    int w = t >> 5;
    if ((t & 31) == 0){ ws[w] = s; ws2[w] = s2; }
    __syncthreads();
    s  = ws[0] + ws[1] + ws[2] + ws[3];
    s2 = ws2[0] + ws2[1] + ws2[2] + ws2[3];
    float m = s * (1.f/C);
    float v = s2 * (1.f/C) - m*m;
    float r = rsqrtf(v + 1e-5f);
    g_zn[p*C + t] = f2tf32((x - m) * r * lng[t] + lnb[t]);
}

// ---------------- kernel 2: pack projection weights [c][512], tf32-rounded ----------------
__global__ void pack_kernel(const float* __restrict__ Wqkv,
                            const float* __restrict__ Wgate){
    int idx = blockIdx.x * blockDim.x + threadIdx.x;
    if (idx >= C*NW2) return;
    int c = idx / NW2, n = idx % NW2;
    float v = (n < 384) ? Wqkv[c*384 + n] : Wgate[c*128 + (n-384)];
    g_W[idx] = f2tf32(v);
}

// ---------------- kernel 3: pair bias (zn @ Wpair), one warp per position ----------------
__global__ void pair_kernel(const float* __restrict__ Wpair){
    int wid = threadIdx.x >> 5;
    int lane = threadIdx.x & 31;
    int p = blockIdx.x * 8 + wid;
    float4 zz = *(const float4*)&g_zn[(size_t)p*C + lane*4];
    float s0 = 0.f, s1 = 0.f, s2 = 0.f, s3 = 0.f;
    #pragma unroll
    for (int k = 0; k < 4; k++){
        float zc = (&zz.x)[k];
        const float* wp = &Wpair[(lane*4 + k)*4];
        s0 += zc * wp[0]; s1 += zc * wp[1];
        s2 += zc * wp[2]; s3 += zc * wp[3];
    }
    #pragma unroll
    for (int o = 16; o; o >>= 1){
        s0 += __shfl_xor_sync(0xFFFFFFFFu, s0, o);
        s1 += __shfl_xor_sync(0xFFFFFFFFu, s1, o);
        s2 += __shfl_xor_sync(0xFFFFFFFFu, s2, o);
        s3 += __shfl_xor_sync(0xFFFFFFFFu, s3, o);
    }
    if (lane < 4){
        float sv = (lane == 0) ? s0 : (lane == 1) ? s1 : (lane == 2) ? s2 : s3;
        int i = p / L, j = p - i*L;
        g_pbI[((size_t)(lane*L + i))*L + j] = sv;
    }
}

// ---------------- kernel 4: projection GEMM via tf32 mma.sync ----------------
// M=102400, N=512, K=128. BM=128, BN=64, full-K smem resident.
// 8 warps = 4 m-warps x 2 n-warps; warp tile m32 x n32 (2 x 4 m16n8k8 tiles).
#define AS_STRIDE 132
#define WS_STRIDE 72
#define GEMM0_SMEM ((128*AS_STRIDE + 128*WS_STRIDE)*4)

__device__ __forceinline__ void epi2(int p, int n, float v0, float v1,
                                     const float* __restrict__ bgate){
    int r = p / L, i = p - r*L;
    if (n < 384){
        int part = n >> 7, rem = n & 127;
        int h = rem >> 5, d = rem & 31;
        size_t idx = ((size_t)(r*H + h)*L + i)*D + d;
        if (part == 0){
            g_q[idx]   = v0 * 0.17677669529663687f;
            g_q[idx+1] = v1 * 0.17677669529663687f;
        } else if (part == 1){
            g_k[idx] = v0; g_k[idx+1] = v1;
        } else {
            g_v[idx] = v0; g_v[idx+1] = v1;
        }
    } else {
        int c = n - 384;
        g_gate[(size_t)p*C + c    ] = 1.f / (1.f + __expf(-(v0 + bgate[c])));
        g_gate[(size_t)p*C + c + 1] = 1.f / (1.f + __expf(-(v1 + bgate[c+1])));
    }
}

__global__ void __launch_bounds__(256)
gemm0_mma(const float* __restrict__ bgate){
    extern __shared__ float smf[];
    float* As = smf;                   // [128][132]
    float* Ws = smf + 128*AS_STRIDE;   // [128][72]

    const int tid = threadIdx.x;
    const int n0 = blockIdx.x * 64;
    const int m0 = blockIdx.y * 128;
    const int lane = tid & 31, wid = tid >> 5;
    const int g = lane >> 2, qr = lane & 3;
    const int wm = (wid & 3) * 32;
    const int wn = (wid >> 2) * 32;

    // fill A (128x128) and W (128x64) tiles
    {
        const float4* ag = (const float4*)&g_zn[(size_t)m0*C];
        #pragma unroll
        for (int u = tid; u < 4096; u += 256){
            int row = u >> 5, c4 = (u & 31) << 2;
            *(float4*)&As[row*AS_STRIDE + c4] = ag[u];
        }
        #pragma unroll
        for (int u = tid; u < 2048; u += 256){
            int row = u >> 4, c4 = (u & 15) << 2;
            *(float4*)&Ws[row*WS_STRIDE + c4] =
                *(const float4*)&g_W[row*NW2 + n0 + c4];
        }
    }
    __syncthreads();

    float o[2][4][4];
    #pragma unroll
    for (int mt = 0; mt < 2; mt++)
        #pragma unroll
        for (int nt = 0; nt < 4; nt++)
            #pragma unroll
            for (int q = 0; q < 4; q++) o[mt][nt][q] = 0.f;

    #pragma unroll
    for (int kt = 0; kt < 16; kt++){
        uint32_t a[2][4], b[4][2];
        #pragma unroll
        for (int mt = 0; mt < 2; mt++){
            const float* ap = &As[(wm + mt*16)*AS_STRIDE + kt*8];
            a[mt][0] = __float_as_uint(ap[(g   )*AS_STRIDE + qr    ]);
            a[mt][1] = __float_as_uint(ap[(g+8 )*AS_STRIDE + qr    ]);
            a[mt][2] = __float_as_uint(ap[(g   )*AS_STRIDE + qr + 4]);
            a[mt][3] = __float_as_uint(ap[(g+8 )*AS_STRIDE + qr + 4]);
        }
        #pragma unroll
        for (int nt = 0; nt < 4; nt++){
            const float* wp = &Ws[(kt*8)*WS_STRIDE + wn + nt*8 + g];
            b[nt][0] = __float_as_uint(wp[(qr  )*WS_STRIDE]);
            b[nt][1] = __float_as_uint(wp[(qr+4)*WS_STRIDE]);
        }
        #pragma unroll
        for (int mt = 0; mt < 2; mt++)
            #pragma unroll
            for (int nt = 0; nt < 4; nt++)
                mma8(o[mt][nt][0], o[mt][nt][1], o[mt][nt][2], o[mt][nt][3],
                     a[mt][0], a[mt][1], a[mt][2], a[mt][3],
                     b[nt][0], b[nt][1]);
    }

    #pragma unroll
    for (int mt = 0; mt < 2; mt++){
        #pragma unroll
        for (int nt = 0; nt < 4; nt++){
            int n = n0 + wn + nt*8 + qr*2;
            int ma = m0 + wm + mt*16 + g;
            epi2(ma,     n, o[mt][nt][0], o[mt][nt][1], bgate);
            epi2(ma + 8, n, o[mt][nt][2], o[mt][nt][3], bgate);
        }
    }
}

// ---------------- kernel 5: tf32 mma.sync flash attention (unchanged) ----------------
#define KV_STRIDE 36
#define SMEM_ATTN (2*L*KV_STRIDE*4)

__global__ void __launch_bounds__(640, 1)
attn_kernel(){
    extern __shared__ float sm[];
    float* Ks = sm;
    float* Vs = sm + L*KV_STRIDE;

    const int tid = threadIdx.x;
    const int lane = tid & 31;
    const int g = lane >> 2;
    const int qr = lane & 3;
    const int i0 = (tid >> 5) * 16;
    const int r = blockIdx.x, h = blockIdx.y;
    const int rh = r*H + h;

    {
        const float4* kg = (const float4*)&g_k[(size_t)rh*L*D];
        const float4* vg = (const float4*)&g_v[(size_t)rh*L*D];
        for (int u = tid; u < L*D/4; u += 640){
            int j = u >> 3, d4 = (u & 7) << 2;
            float4 kv = kg[u];
            float4 vv = vg[u];
            float* kd = &Ks[j*KV_STRIDE + d4];
            float* vd = &Vs[j*KV_STRIDE + d4];
            kd[0] = f2tf32(kv.x); kd[1] = f2tf32(kv.y);
            kd[2] = f2tf32(kv.z); kd[3] = f2tf32(kv.w);
            vd[0] = f2tf32(vv.x); vd[1] = f2tf32(vv.y);
            vd[2] = f2tf32(vv.z); vd[3] = f2tf32(vv.w);
        }
    }

    uint32_t qa[4][4];
    {
        const float* qbase = g_q + ((size_t)rh*L + i0)*D;
        #pragma unroll
        for (int t = 0; t < 4; t++){
            qa[t][0] = __float_as_uint(f2tf32(__ldg(&qbase[(g   )*D + 8*t + qr    ])));
            qa[t][1] = __float_as_uint(f2tf32(__ldg(&qbase[(g+8 )*D + 8*t + qr    ])));
            qa[t][2] = __float_as_uint(f2tf32(__ldg(&qbase[(g   )*D + 8*t + qr + 4])));
            qa[t][3] = __float_as_uint(f2tf32(__ldg(&qbase[(g+8 )*D + 8*t + qr + 4])));
        }
    }
    __syncthreads();

    const float* bp0 = g_pbI + ((size_t)(h*L + i0 + g    ))*L;
    const float* bp1 = g_pbI + ((size_t)(h*L + i0 + g + 8))*L;

    float o[4][4];
    #pragma unroll
    for (int n = 0; n < 4; n++)
        #pragma unroll
        for (int q = 0; q < 4; q++) o[n][q] = 0.f;
    float lsum0 = 0.f, lsum1 = 0.f;

    const int srcA = (lane & ~3) | (qr >> 1);
    const int srcB = srcA + 2;
    const bool oddl = lane & 1;

    for (int c = 0; c < 5; c++){
        const int jc = 64*c;
        float pr0[8], pr1[8], pr2[8], pr3[8];
        #pragma unroll
        for (int n = 0; n < 8; n++){
            float s0 = 0.f, s1 = 0.f, s2 = 0.f, s3 = 0.f;
            const float* kb = &Ks[(jc + 8*n + g)*KV_STRIDE + qr];
            #pragma unroll
            for (int t = 0; t < 4; t++){
                uint32_t b0 = __float_as_uint(kb[8*t]);
                uint32_t b1 = __float_as_uint(kb[8*t + 4]);
                mma8(s0, s1, s2, s3, qa[t][0], qa[t][1], qa[t][2], qa[t][3], b0, b1);
            }
            int j0 = jc + 8*n + qr*2;
            float2 ba = *(const float2*)&bp0[j0];
            float2 bb = *(const float2*)&bp1[j0];
            float p0 = f2tf32(__expf(fminf(s0 + ba.x, 60.f)));
            float p1 = f2tf32(__expf(fminf(s1 + ba.y, 60.f)));
            float p2 = f2tf32(__expf(fminf(s2 + bb.x, 60.f)));
            float p3 = f2tf32(__expf(fminf(s3 + bb.y, 60.f)));
            lsum0 += p0 + p1;
            lsum1 += p2 + p3;
            pr0[n] = p0; pr1[n] = p1; pr2[n] = p2; pr3[n] = p3;
        }
        #pragma unroll
        for (int t = 0; t < 8; t++){
            float v0a = __shfl_sync(0xFFFFFFFFu, pr0[t], srcA);
            float v1a = __shfl_sync(0xFFFFFFFFu, pr1[t], srcA);
            float v2a = __shfl_sync(0xFFFFFFFFu, pr2[t], srcA);
            float v3a = __shfl_sync(0xFFFFFFFFu, pr3[t], srcA);
            float v0b = __shfl_sync(0xFFFFFFFFu, pr0[t], srcB);
            float v1b = __shfl_sync(0xFFFFFFFFu, pr1[t], srcB);
            float v2b = __shfl_sync(0xFFFFFFFFu, pr2[t], srcB);
            float v3b = __shfl_sync(0xFFFFFFFFu, pr3[t], srcB);
            uint32_t A0 = __float_as_uint(oddl ? v1a : v0a);
            uint32_t A1 = __float_as_uint(oddl ? v3a : v2a);
            uint32_t A2 = __float_as_uint(oddl ? v1b : v0b);
            uint32_t A3 = __float_as_uint(oddl ? v3b : v2b);
            const float* vb0 = &Vs[(jc + 8*t + qr    )*KV_STRIDE + g];
            const float* vb1 = &Vs[(jc + 8*t + qr + 4)*KV_STRIDE + g];
            #pragma unroll
            for (int n = 0; n < 4; n++){
                uint32_t b0 = __float_as_uint(vb0[8*n]);
                uint32_t b1 = __float_as_uint(vb1[8*n]);
                mma8(o[n][0], o[n][1], o[n][2], o[n][3], A0, A1, A2, A3, b0, b1);
            }
        }
    }

    lsum0 += __shfl_xor_sync(0xFFFFFFFFu, lsum0, 1);
    lsum0 += __shfl_xor_sync(0xFFFFFFFFu, lsum0, 2);
    lsum1 += __shfl_xor_sync(0xFFFFFFFFu, lsum1, 1);
    lsum1 += __shfl_xor_sync(0xFFFFFFFFu, lsum1, 2);
    float inv0 = 1.f / lsum0;
    float inv1 = 1.f / lsum1;

    int ig0 = i0 + g, ig1 = i0 + g + 8;
    size_t ob0 = (size_t)(r*L + ig0)*C + h*D;
    size_t ob1 = (size_t)(r*L + ig1)*C + h*D;
    #pragma unroll
    for (int n = 0; n < 4; n++){
        int d0 = 8*n + qr*2;
        float2 g0 = *(const float2*)&g_gate[ob0 + d0];
        float2 g1 = *(const float2*)&g_gate[ob1 + d0];
        float2 w0, w1;
        w0.x = o[n][0] * inv0 * g0.x;
        w0.y = o[n][1] * inv0 * g0.y;
        w1.x = o[n][2] * inv1 * g1.x;
        w1.y = o[n][3] * inv1 * g1.y;
        *(float2*)&g_att[ob0 + d0] = w0;
        *(float2*)&g_att[ob1 + d0] = w1;
    }
}

// ---------------- kernel 6: output GEMM (FFMA2, fp32, N=128) ----------------
__global__ void __launch_bounds__(256)
gemm1_kernel(const float* __restrict__ W,
             const float* __restrict__ bias,
             float* __restrict__ out){
    const float* __restrict__ A = g_att;
    const int n0 = blockIdx.x * 64;
    const int m0 = blockIdx.y * 128;
    __shared__ float As[32][132];
    __shared__ float Ws[32][68];

    int tid = threadIdx.x;
    int tx = tid & 15;
    int ty = tid >> 4;

    ull acc[4][4];
    #pragma unroll
    for (int a = 0; a < 4; a++)
        #pragma unroll
        for (int b = 0; b < 4; b++) acc[a][b] = 0ull;

    for (int kc = 0; kc < 128; kc += 32){
        #pragma unroll
        for (int t = tid; t < 1024; t += 256){
            int m = t >> 3, c4 = (t & 7) * 4;
            float4 a = *(const float4*)&A[(size_t)(m0 + m)*C + kc + c4];
            As[c4+0][m] = a.x; As[c4+1][m] = a.y;
            As[c4+2][m] = a.z; As[c4+3][m] = a.w;
        }
        #pragma unroll
        for (int t = tid; t < 512; t += 256){
            int c = t >> 4, n4 = (t & 15) * 4;
            *(float4*)&Ws[c][n4] = *(const float4*)&W[(kc + c)*128 + n0 + n4];
        }
        __syncthreads();

        #pragma unroll 8
        for (int k = 0; k < 32; k++){
            ulonglong2 a01 = *(const ulonglong2*)&As[k][ty*8];
            ulonglong2 a23 = *(const ulonglong2*)&As[k][ty*8 + 4];
            float4 b = *(const float4*)&Ws[k][tx*4];
            ull bs0 = pack2(b.x, b.x), bs1 = pack2(b.y, b.y);
            ull bs2 = pack2(b.z, b.z), bs3 = pack2(b.w, b.w);
            acc[0][0] = ffma2(a01.x, bs0, acc[0][0]);
            acc[0][1] = ffma2(a01.x, bs1, acc[0][1]);
            acc[0][2] = ffma2(a01.x, bs2, acc[0][2]);
            acc[0][3] = ffma2(a01.x, bs3, acc[0][3]);
            acc[1][0] = ffma2(a01.y, bs0, acc[1][0]);
            acc[1][1] = ffma2(a01.y, bs1, acc[1][1]);
            acc[1][2] = ffma2(a01.y, bs2, acc[1][2]);
            acc[1][3] = ffma2(a01.y, bs3, acc[1][3]);
            acc[2][0] = ffma2(a23.x, bs0, acc[2][0]);
            acc[2][1] = ffma2(a23.x, bs1, acc[2][1]);
            acc[2][2] = ffma2(a23.x, bs2, acc[2][2]);
            acc[2][3] = ffma2(a23.x, bs3, acc[2][3]);
            acc[3][0] = ffma2(a23.y, bs0, acc[3][0]);
            acc[3][1] = ffma2(a23.y, bs1, acc[3][1]);
            acc[3][2] = ffma2(a23.y, bs2, acc[3][2]);
            acc[3][3] = ffma2(a23.y, bs3, acc[3][3]);
        }
        __syncthreads();
    }

    #pragma unroll
    for (int mp = 0; mp < 4; mp++){
        int m = m0 + ty*8 + mp*2;
        #pragma unroll
        for (int j = 0; j < 4; j++){
            int n = n0 + tx*4 + j;
            float2 v2 = unpack2(acc[mp][j]);
            float bb = bias[n];
            out[(size_t)(m  )*C + n] = v2.x + bb;
            out[(size_t)(m+1)*C + n] = v2.y + bb;
        }
    }
}

// ---------------- launch ----------------
extern "C" void kernel_launch(void* const* d_in, const int* in_sizes, int n_in,
                              void* d_out, int out_size){
    const float* z     = (const float*)d_in[0];
    const float* ln_g  = (const float*)d_in[1];
    const float* ln_b  = (const float*)d_in[2];
    const float* Wqkv  = (const float*)d_in[3];
    const float* Wpair = (const float*)d_in[4];
    const float* Wgate = (const float*)d_in[5];
    const float* bgate = (const float*)d_in[6];
    const float* Wout  = (const float*)d_in[7];
    const float* bout  = (const float*)d_in[8];
    float* out = (float*)d_out;

    static bool attr_set = false;
    if (!attr_set){
        cudaFuncSetAttribute(attn_kernel, cudaFuncAttributeMaxDynamicSharedMemorySize,
                             SMEM_ATTN);
        cudaFuncSetAttribute(gemm0_mma, cudaFuncAttributeMaxDynamicSharedMemorySize,
                             GEMM0_SMEM);
        attr_set = true;
    }

    ln_kernel<<<NPOS, 128>>>(z, ln_g, ln_b);
    pack_kernel<<<(C*NW2 + 255)/256, 256>>>(Wqkv, Wgate);
    pair_kernel<<<NPOS/8, 256>>>(Wpair);
    gemm0_mma<<<dim3(NW2/64, NPOS/128), 256, GEMM0_SMEM>>>(bgate);
    attn_kernel<<<dim3(L, H), 640, SMEM_ATTN>>>();
    gemm1_kernel<<<dim3(2, NPOS/128), 256>>>(Wout, bout, out);
}